// round 13
// baseline (speedup 1.0000x reference)
#include <cuda_runtime.h>

// x [B=4096, T=512, D=4], H=32, 2 stacked LSTM layers, gate rows i,f,g,o (0..127),
// head: out[b] = h2[T-1] . W_out + b_out.
// R7 base config (3 blocks/SM, weights in regs, FFMA2, MUFU.TANH, partitioned
// updates, 2 barriers/step) extended to THREE batches per block (A,B,C) with
// lean per-batch accumulators and rotated x prefetch. Waves 4.61 -> 3.08.
#define TT 512
#define DD 4

typedef unsigned long long ull;

__device__ __forceinline__ ull ffma2(ull a, ull b, ull c) {
    ull d;
    asm("fma.rn.f32x2 %0, %1, %2, %3;" : "=l"(d) : "l"(a), "l"(b), "l"(c));
    return d;
}
__device__ __forceinline__ ull fadd2(ull a, ull b) {
    ull d;
    asm("add.rn.f32x2 %0, %1, %2;" : "=l"(d) : "l"(a), "l"(b));
    return d;
}
__device__ __forceinline__ ull fpack(float lo, float hi) {
    ull d;
    asm("mov.b64 %0, {%1, %2};" : "=l"(d) : "f"(lo), "f"(hi));
    return d;
}
__device__ __forceinline__ float funpack_sum(ull p) {
    float lo, hi;
    asm("mov.b64 {%0, %1}, %2;" : "=f"(lo), "=f"(hi) : "l"(p));
    return lo + hi;
}

__device__ __forceinline__ float tanh_hw(float x) {
    float y;
    asm("tanh.approx.f32 %0, %1;" : "=f"(y) : "f"(x));
    return y;
}
__device__ __forceinline__ float fsig(float x) {
    return fmaf(0.5f, tanh_hw(0.5f * x), 0.5f);
}
__device__ __forceinline__ float ftanh(float x) { return tanh_hw(x); }

#define NBATCH 3

__global__ __launch_bounds__(128, 3)
void lstm2_kernel(const float* __restrict__ x,
                  const float* __restrict__ Wih0, const float* __restrict__ Whh0,
                  const float* __restrict__ bih0, const float* __restrict__ bhh0,
                  const float* __restrict__ Wih1, const float* __restrict__ Whh1,
                  const float* __restrict__ bih1, const float* __restrict__ bhh1,
                  const float* __restrict__ Wout, const float* __restrict__ bout,
                  float* __restrict__ out, int Btot)
{
    const int b0   = blockIdx.x * NBATCH;
    const int tid  = threadIdx.x;          // gate-row index for the dots
    const int gate = tid >> 5;             // warp id: gate row-group & update tasks
    const int lane = tid & 31;

    // H/G index: 0=(L1,A) 1=(L1,B) 2=(L1,C) 3=(L0,A) 4=(L0,B) 5=(L0,C)
    __shared__ __align__(16) float H[6][32];
    __shared__ float G[6][128];

    // ---- weights resident as f32x2 register pairs, shared by all 3 streams ----
    ull wih0p[2], whh0p[16], wih1p[16], whh1p[16];
    {
        const ulonglong2* r;
        r = reinterpret_cast<const ulonglong2*>(Wih0 + tid * 4);
        { ulonglong2 v = r[0]; wih0p[0] = v.x; wih0p[1] = v.y; }
        r = reinterpret_cast<const ulonglong2*>(Whh0 + tid * 32);
        #pragma unroll
        for (int k = 0; k < 8; ++k) { ulonglong2 v = r[k]; whh0p[2*k] = v.x; whh0p[2*k+1] = v.y; }
        r = reinterpret_cast<const ulonglong2*>(Wih1 + tid * 32);
        #pragma unroll
        for (int k = 0; k < 8; ++k) { ulonglong2 v = r[k]; wih1p[2*k] = v.x; wih1p[2*k+1] = v.y; }
        r = reinterpret_cast<const ulonglong2*>(Whh1 + tid * 32);
        #pragma unroll
        for (int k = 0; k < 8; ++k) { ulonglong2 v = r[k]; whh1p[2*k] = v.x; whh1p[2*k+1] = v.y; }
    }
    const ull bias0p = fpack(bih0[tid] + bhh0[tid], 0.0f);
    const ull bias1p = fpack(bih1[tid] + bhh1[tid], 0.0f);
    const ull ZP = 0ull;

    // update tasks: warp w -> task w; warps 0,1 additionally -> tasks 4,5
    const int task2 = (gate < 2) ? (4 + gate) : -1;
    float cst1 = 0.0f, cst2 = 0.0f;

    if (tid < 32) {
        #pragma unroll
        for (int a = 0; a < 6; ++a) H[a][tid] = 0.0f;
    }
    __syncthreads();

    // batch x pointers (clamped for the possibly-partial last block)
    const ulonglong2* Xb = reinterpret_cast<const ulonglong2*>(x);
    const ulonglong2* XA = Xb + (size_t)b0 * TT;
    const ulonglong2* XB = (b0 + 1 < Btot) ? XA + TT     : XA;
    const ulonglong2* XC = (b0 + 2 < Btot) ? XA + 2 * TT : XA;

    const ulonglong2* H1A = reinterpret_cast<const ulonglong2*>(H[0]);
    const ulonglong2* H1B = reinterpret_cast<const ulonglong2*>(H[1]);
    const ulonglong2* H1C = reinterpret_cast<const ulonglong2*>(H[2]);
    const ulonglong2* H0A = reinterpret_cast<const ulonglong2*>(H[3]);
    const ulonglong2* H0B = reinterpret_cast<const ulonglong2*>(H[4]);
    const ulonglong2* H0C = reinterpret_cast<const ulonglong2*>(H[5]);

    // ================= prologue: layer-0 gates for step 0 (h0 == 0) =================
    {
        ulonglong2 xa = XA[0], xb = XB[0], xc = XC[0];
        float pA = funpack_sum(fadd2(ffma2(xa.x, wih0p[0], bias0p),
                                     ffma2(xa.y, wih0p[1], ZP)));
        float pB = funpack_sum(fadd2(ffma2(xb.x, wih0p[0], bias0p),
                                     ffma2(xb.y, wih0p[1], ZP)));
        float pC = funpack_sum(fadd2(ffma2(xc.x, wih0p[0], bias0p),
                                     ffma2(xc.y, wih0p[1], ZP)));
        if (gate == 2) {
            G[3][tid] = ftanh(pA); G[4][tid] = ftanh(pB); G[5][tid] = ftanh(pC);
        } else {
            G[3][tid] = fsig(pA);  G[4][tid] = fsig(pB);  G[5][tid] = fsig(pC);
        }
    }
    ulonglong2 xvA = XA[1], xvB = XB[1], xvC = XC[1];   // x for step 1
    __syncthreads();
    // step-0 L0 updates: task 3 on warp3 (slot1), tasks 4,5 on warps 0,1 (slot2)
    if (gate == 3) {
        const float* gs = G[3];
        float gi = gs[lane], gf = gs[32+lane], gg = gs[64+lane], go = gs[96+lane];
        cst1 = fmaf(gf, cst1, gi * gg);
        H[3][lane] = go * tanh_hw(cst1);
    }
    if (task2 >= 0) {
        const float* gs = G[task2];
        float gi = gs[lane], gf = gs[32+lane], gg = gs[64+lane], go = gs[96+lane];
        cst2 = fmaf(gf, cst2, gi * gg);
        H[task2][lane] = go * tanh_hw(cst2);
    }
    __syncthreads();

    // ===== main loop: dots(3 batches) -> rotate x -> BAR -> updates -> BAR =====
    for (int t = 0; t < TT - 1; ++t) {
        ull sA0 = bias0p, sA1 = ZP, sB0 = bias0p, sB1 = ZP, sC0 = bias0p, sC1 = ZP;
        ull uA0 = bias1p, uA1 = ZP, uB0 = bias1p, uB1 = ZP, uC0 = bias1p, uC1 = ZP;
        #pragma unroll
        for (int k = 0; k < 8; ++k) {
            ulonglong2 aA = H0A[k], hA = H1A[k];
            uA0 = ffma2(aA.x, wih1p[2*k],   uA0);
            uA1 = ffma2(aA.y, wih1p[2*k+1], uA1);
            uA0 = ffma2(hA.x, whh1p[2*k],   uA0);
            uA1 = ffma2(hA.y, whh1p[2*k+1], uA1);
            sA0 = ffma2(aA.x, whh0p[2*k],   sA0);
            sA1 = ffma2(aA.y, whh0p[2*k+1], sA1);
            ulonglong2 aB = H0B[k], hB = H1B[k];
            uB0 = ffma2(aB.x, wih1p[2*k],   uB0);
            uB1 = ffma2(aB.y, wih1p[2*k+1], uB1);
            uB0 = ffma2(hB.x, whh1p[2*k],   uB0);
            uB1 = ffma2(hB.y, whh1p[2*k+1], uB1);
            sB0 = ffma2(aB.x, whh0p[2*k],   sB0);
            sB1 = ffma2(aB.y, whh0p[2*k+1], sB1);
            ulonglong2 aC = H0C[k], hC = H1C[k];
            uC0 = ffma2(aC.x, wih1p[2*k],   uC0);
            uC1 = ffma2(aC.y, wih1p[2*k+1], uC1);
            uC0 = ffma2(hC.x, whh1p[2*k],   uC0);
            uC1 = ffma2(hC.y, whh1p[2*k+1], uC1);
            sC0 = ffma2(aC.x, whh0p[2*k],   sC0);
            sC1 = ffma2(aC.y, whh0p[2*k+1], sC1);
        }
        // consume x(t+1), then immediately rotate-load x(t+2) (full-step cover)
        sA0 = ffma2(xvA.x, wih0p[0], sA0);
        sA1 = ffma2(xvA.y, wih0p[1], sA1);
        sB0 = ffma2(xvB.x, wih0p[0], sB0);
        sB1 = ffma2(xvB.y, wih0p[1], sB1);
        sC0 = ffma2(xvC.x, wih0p[0], sC0);
        sC1 = ffma2(xvC.y, wih0p[1], sC1);
        {
            const int ti = (t + 2 < TT) ? (t + 2) : (TT - 1);
            xvA = XA[ti]; xvB = XB[ti]; xvC = XC[ti];
        }

        float pA1 = funpack_sum(fadd2(uA0, uA1));
        float pB1 = funpack_sum(fadd2(uB0, uB1));
        float pC1 = funpack_sum(fadd2(uC0, uC1));
        float pA0 = funpack_sum(fadd2(sA0, sA1));
        float pB0 = funpack_sum(fadd2(sB0, sB1));
        float pC0 = funpack_sum(fadd2(sC0, sC1));

        if (gate == 2) {
            G[0][tid] = ftanh(pA1); G[1][tid] = ftanh(pB1); G[2][tid] = ftanh(pC1);
            G[3][tid] = ftanh(pA0); G[4][tid] = ftanh(pB0); G[5][tid] = ftanh(pC0);
        } else {
            G[0][tid] = fsig(pA1);  G[1][tid] = fsig(pB1);  G[2][tid] = fsig(pC1);
            G[3][tid] = fsig(pA0);  G[4][tid] = fsig(pB0);  G[5][tid] = fsig(pC0);
        }
        __syncthreads();                      // BAR1: gates visible

        {   // task 1: warp w -> (G[w] -> H[w])
            const float* gs = G[gate];
            float gi = gs[lane], gf = gs[32+lane], gg = gs[64+lane], go = gs[96+lane];
            cst1 = fmaf(gf, cst1, gi * gg);
            H[gate][lane] = go * tanh_hw(cst1);
        }
        if (task2 >= 0) {   // task 2: warps 0,1 -> tasks 4,5
            const float* gs = G[task2];
            float gi = gs[lane], gf = gs[32+lane], gg = gs[64+lane], go = gs[96+lane];
            cst2 = fmaf(gf, cst2, gi * gg);
            H[task2][lane] = go * tanh_hw(cst2);
        }
        __syncthreads();                      // BAR2: h visible for next dots
    }

    // ================= epilogue: L1(TT-1), all batches =================
    {
        ull uA0 = bias1p, uA1 = ZP, uB0 = bias1p, uB1 = ZP, uC0 = bias1p, uC1 = ZP;
        #pragma unroll
        for (int k = 0; k < 8; ++k) {
            ulonglong2 aA = H0A[k], hA = H1A[k];
            uA0 = ffma2(aA.x, wih1p[2*k],   uA0);
            uA1 = ffma2(aA.y, wih1p[2*k+1], uA1);
            uA0 = ffma2(hA.x, whh1p[2*k],   uA0);
            uA1 = ffma2(hA.y, whh1p[2*k+1], uA1);
            ulonglong2 aB = H0B[k], hB = H1B[k];
            uB0 = ffma2(aB.x, wih1p[2*k],   uB0);
            uB1 = ffma2(aB.y, wih1p[2*k+1], uB1);
            uB0 = ffma2(hB.x, whh1p[2*k],   uB0);
            uB1 = ffma2(hB.y, whh1p[2*k+1], uB1);
            ulonglong2 aC = H0C[k], hC = H1C[k];
            uC0 = ffma2(aC.x, wih1p[2*k],   uC0);
            uC1 = ffma2(aC.y, wih1p[2*k+1], uC1);
            uC0 = ffma2(hC.x, whh1p[2*k],   uC0);
            uC1 = ffma2(hC.y, whh1p[2*k+1], uC1);
        }
        float pA1 = funpack_sum(fadd2(uA0, uA1));
        float pB1 = funpack_sum(fadd2(uB0, uB1));
        float pC1 = funpack_sum(fadd2(uC0, uC1));
        if (gate == 2) {
            G[0][tid] = ftanh(pA1); G[1][tid] = ftanh(pB1); G[2][tid] = ftanh(pC1);
        } else {
            G[0][tid] = fsig(pA1);  G[1][tid] = fsig(pB1);  G[2][tid] = fsig(pC1);
        }
    }
    __syncthreads();
    if (gate < 3) {   // final L1 updates: tasks 0,1,2 on warps 0,1,2
        const float* gs = G[gate];
        float gi = gs[lane], gf = gs[32+lane], gg = gs[64+lane], go = gs[96+lane];
        cst1 = fmaf(gf, cst1, gi * gg);
        H[gate][lane] = go * tanh_hw(cst1);
    }
    __syncthreads();

    // -------- head: warps 0..2 each reduce their batch --------
    if (gate < 3) {
        int b = b0 + gate;
        float v = H[gate][lane] * Wout[lane];
        #pragma unroll
        for (int o = 16; o > 0; o >>= 1)
            v += __shfl_down_sync(0xffffffffu, v, o);
        if (lane == 0 && b < Btot) out[b] = v + bout[0];
    }
}

extern "C" void kernel_launch(void* const* d_in, const int* in_sizes, int n_in,
                              void* d_out, int out_size)
{
    const float* x    = (const float*)d_in[0];
    const float* Wih0 = (const float*)d_in[1];
    const float* Whh0 = (const float*)d_in[2];
    const float* bih0 = (const float*)d_in[3];
    const float* bhh0 = (const float*)d_in[4];
    const float* Wih1 = (const float*)d_in[5];
    const float* Whh1 = (const float*)d_in[6];
    const float* bih1 = (const float*)d_in[7];
    const float* bhh1 = (const float*)d_in[8];
    const float* Wout = (const float*)d_in[9];
    const float* bout = (const float*)d_in[10];

    const int B  = out_size;                 // 4096
    const int nb = (B + NBATCH - 1) / NBATCH;  // 1366
    lstm2_kernel<<<nb, 128>>>(x, Wih0, Whh0, bih0, bhh0,
                              Wih1, Whh1, bih1, bhh1,
                              Wout, bout, (float*)d_out, B);
}

// round 15
// speedup vs baseline: 1.3055x; 1.3055x over previous
#include <cuda_runtime.h>
#include <cuda_bf16.h>
#include <cstdint>
typedef uint32_t u32;
typedef uint16_t u16;

#define TT 512
#define PB 80            // B plane pitch (32 bf16 + pad), conflict-free for ldmatrix
#define PG 144           // gates plane pitch (32 f32 + pad)
#define OFF_BLO 6400     // B planes: hi at 0, lo at 6400 (80 rows x 80B)
#define OFF_G0  12800
#define OFF_G1  31232
#define SMEM_SZ 49664

static __device__ __forceinline__ float th(float x){float y;asm("tanh.approx.f32 %0,%1;":"=f"(y):"f"(x));return y;}
static __device__ __forceinline__ float sg(float x){return fmaf(0.5f,th(0.5f*x),0.5f);}
static __device__ __forceinline__ u16 bfb(float v){__nv_bfloat16 h=__float2bfloat16(v);return *reinterpret_cast<u16*>(&h);}
static __device__ __forceinline__ float bff(u16 b){__nv_bfloat16 h=*reinterpret_cast<__nv_bfloat16*>(&b);return __bfloat162float(h);}

#define MMA(d0,d1,d2,d3,a,b0,b1) \
  asm volatile("mma.sync.aligned.m16n8k16.row.col.f32.bf16.bf16.f32 " \
    "{%0,%1,%2,%3},{%4,%5,%6,%7},{%8,%9},{%0,%1,%2,%3};" \
    : "+f"(d0),"+f"(d1),"+f"(d2),"+f"(d3) \
    : "r"((a)[0]),"r"((a)[1]),"r"((a)[2]),"r"((a)[3]),"r"(b0),"r"(b1))

static __device__ __forceinline__ void ldm4(u32* r, u32 a){
  asm volatile("ldmatrix.sync.aligned.m8n8.x4.trans.shared.b16 {%0,%1,%2,%3},[%4];"
    : "=r"(r[0]),"=r"(r[1]),"=r"(r[2]),"=r"(r[3]) : "r"(a));
}
static __device__ __forceinline__ u32 su32(const void*p){u32 a;asm("{.reg .u64 t;cvta.to.shared.u64 t,%1;cvt.u32.u64 %0,t;}":"=r"(a):"l"(p));return a;}

// A matrices: A0[r][k]: k<32 -> Whh0, k in [64,68) -> Wih0, else 0  (K-chunks 0,1,4)
//             A1[r][k]: k<32 -> Wih1, k in [32,64) -> Whh1          (K-chunks 0..3)
static __device__ __forceinline__ float A0v(const float* Whh0,const float* Wih0,int r,int k){
  if(k<32) return Whh0[r*32+k];
  if(k>=64&&k<68) return Wih0[r*4+(k-64)];
  return 0.f;
}
static __device__ __forceinline__ float A1v(const float* Wih1,const float* Whh1,int r,int k){
  return (k<32) ? Wih1[r*32+k] : Whh1[r*32+(k-32)];
}

__global__ __launch_bounds__(256,1)
void lstm_k(const float* __restrict__ x,
            const float* __restrict__ Wih0,const float* __restrict__ Whh0,
            const float* __restrict__ bih0,const float* __restrict__ bhh0,
            const float* __restrict__ Wih1,const float* __restrict__ Whh1,
            const float* __restrict__ bih1,const float* __restrict__ bhh1,
            const float* __restrict__ Wout,const float* __restrict__ bout,
            float* __restrict__ out)
{
  extern __shared__ __align__(16) char smc[];
  const u32 sb = su32(smc);
  const int tid=threadIdx.x, w=tid>>5, lane=tid&31;
  const int g=lane>>2, tg=lane&3;
  const int r0=16*w+g, r1=r0+8;
  const bool isg = ((w>>1)==2);              // rows 64..95 = gate 'g' -> tanh

  // zero both B planes (h=0 init, x pad rows stay 0)
  for(int i=tid;i<800;i+=256) reinterpret_cast<uint4*>(smc)[i]=make_uint4(0,0,0,0);

  // ---- A fragments in registers (hi/lo bf16 split), built straight from gmem ----
  u32 a0h[3][4],a0l[3][4],a1h[4][4],a1l[4][4];
  {
    const int kb0[3]={0,16,64};
    #pragma unroll
    for(int m=0;m<3;m++)
      #pragma unroll
      for(int j=0;j<4;j++){
        int rr=(j&1)?r1:r0, kk=kb0[m]+2*tg+((j>>1)*8);
        float v0=A0v(Whh0,Wih0,rr,kk), v1=A0v(Whh0,Wih0,rr,kk+1);
        u16 h0=bfb(v0),h1=bfb(v1);
        a0h[m][j]=(u32)h0|((u32)h1<<16);
        a0l[m][j]=(u32)bfb(v0-bff(h0))|((u32)bfb(v1-bff(h1))<<16);
      }
    #pragma unroll
    for(int m=0;m<4;m++)
      #pragma unroll
      for(int j=0;j<4;j++){
        int rr=(j&1)?r1:r0, kk=16*m+2*tg+((j>>1)*8);
        float v0=A1v(Wih1,Whh1,rr,kk), v1=A1v(Wih1,Whh1,rr,kk+1);
        u16 h0=bfb(v0),h1=bfb(v1);
        a1h[m][j]=(u32)h0|((u32)h1<<16);
        a1l[m][j]=(u32)bfb(v0-bff(h0))|((u32)bfb(v1-bff(h1))<<16);
      }
  }
  const float b0A=bih0[r0]+bhh0[r0], b0B=bih0[r1]+bhh0[r1];
  const float b1A=bih1[r0]+bhh1[r0], b1B=bih1[r1]+bhh1[r1];

  // update-task mapping: thread -> (layer l, unit u, batches 8*bg..)
  const int l=tid>>7, uu=(tid>>2)&31, bg=tid&3;
  float c8[8];
  #pragma unroll
  for(int i=0;i<8;++i) c8[i]=0.f;

  // ldmatrix per-lane base offset: tile(kc,ncp) addr = plane + lmoff + kc*16*PB + ncp*16
  const int lj=lane>>3, lr=lane&7;
  const u32 lmoff=(u32)((((lj&1)*8+lr)*PB) + ((lj>>1)*16));

  __syncthreads();

  // x stream: thread n<32 owns batch n
  const float4* xg = reinterpret_cast<const float4*>(x) + ((size_t)(blockIdx.x*32+tid))*TT;
  float4 xreg=make_float4(0,0,0,0);
  if(tid<32){
    float4 v=xg[0]; float vv[4]={v.x,v.y,v.z,v.w};
    #pragma unroll
    for(int k=0;k<4;k++){
      u16 hb=bfb(vv[k]);
      *reinterpret_cast<u16*>(smc+(64+k)*PB+tid*2)=hb;
      *reinterpret_cast<u16*>(smc+OFF_BLO+(64+k)*PB+tid*2)=bfb(vv[k]-bff(hb));
    }
    xreg=xg[1];
  }
  __syncthreads();

  for(int it=-1;it<TT;++it){
    const bool do0=(it<TT-1), do1=(it>=0);
    #pragma unroll
    for(int ncp=0;ncp<4;ncp+=2){
      u32 bh[5][4], bl[5][4];
      #pragma unroll
      for(int kc=0;kc<5;kc++){
        u32 base=lmoff+(u32)(kc*16*PB)+(u32)(ncp*16);
        ldm4(bh[kc], sb+base);
        ldm4(bl[kc], sb+OFF_BLO+base);
      }
      #pragma unroll
      for(int ns=0;ns<2;++ns){
        const int nc=ncp+ns;
        if(do0){
          float d0=b0A,d1=b0A,d2=b0B,d3=b0B;
          #pragma unroll
          for(int m=0;m<3;m++){
            const int kc=(m==2)?4:m;
            MMA(d0,d1,d2,d3,a0h[m],bh[kc][2*ns],bh[kc][2*ns+1]);
            MMA(d0,d1,d2,d3,a0h[m],bl[kc][2*ns],bl[kc][2*ns+1]);
            MMA(d0,d1,d2,d3,a0l[m],bh[kc][2*ns],bh[kc][2*ns+1]);
          }
          float e0,e1,e2,e3;
          if(isg){e0=th(d0);e1=th(d1);e2=th(d2);e3=th(d3);}
          else   {e0=sg(d0);e1=sg(d1);e2=sg(d2);e3=sg(d3);}
          char* gp=smc+OFF_G0+r0*PG+(nc*8+2*tg)*4;
          *reinterpret_cast<float2*>(gp)=make_float2(e0,e1);
          *reinterpret_cast<float2*>(gp+8*PG)=make_float2(e2,e3);
        }
        if(do1){
          float d0=b1A,d1=b1A,d2=b1B,d3=b1B;
          #pragma unroll
          for(int m=0;m<4;m++){
            MMA(d0,d1,d2,d3,a1h[m],bh[m][2*ns],bh[m][2*ns+1]);
            MMA(d0,d1,d2,d3,a1h[m],bl[m][2*ns],bl[m][2*ns+1]);
            MMA(d0,d1,d2,d3,a1l[m],bh[m][2*ns],bh[m][2*ns+1]);
          }
          float e0,e1,e2,e3;
          if(isg){e0=th(d0);e1=th(d1);e2=th(d2);e3=th(d3);}
          else   {e0=sg(d0);e1=sg(d1);e2=sg(d2);e3=sg(d3);}
          char* gp=smc+OFF_G1+r0*PG+(nc*8+2*tg)*4;
          *reinterpret_cast<float2*>(gp)=make_float2(e0,e1);
          *reinterpret_cast<float2*>(gp+8*PG)=make_float2(e2,e3);
        }
      }
    }
    __syncthreads();                      // BAR1: gates visible

    if((l==0&&do0)||(l==1&&do1)){
      const char* gp=smc+(l?OFF_G1:OFF_G0)+uu*PG+bg*32;
      float4 i0=*reinterpret_cast<const float4*>(gp),        i1=*reinterpret_cast<const float4*>(gp+16);
      float4 f0=*reinterpret_cast<const float4*>(gp+32*PG),  f1=*reinterpret_cast<const float4*>(gp+32*PG+16);
      float4 g0=*reinterpret_cast<const float4*>(gp+64*PG),  g1=*reinterpret_cast<const float4*>(gp+64*PG+16);
      float4 o0=*reinterpret_cast<const float4*>(gp+96*PG),  o1=*reinterpret_cast<const float4*>(gp+96*PG+16);
      float I[8]={i0.x,i0.y,i0.z,i0.w,i1.x,i1.y,i1.z,i1.w};
      float F[8]={f0.x,f0.y,f0.z,f0.w,f1.x,f1.y,f1.z,f1.w};
      float Gv[8]={g0.x,g0.y,g0.z,g0.w,g1.x,g1.y,g1.z,g1.w};
      float O[8]={o0.x,o0.y,o0.z,o0.w,o1.x,o1.y,o1.z,o1.w};
      u32 ph[4],pl[4];
      #pragma unroll
      for(int j=0;j<4;j++){
        float h0,h1;
        c8[2*j]  =fmaf(F[2*j],  c8[2*j],  I[2*j]*Gv[2*j]);     h0=O[2*j]*th(c8[2*j]);
        c8[2*j+1]=fmaf(F[2*j+1],c8[2*j+1],I[2*j+1]*Gv[2*j+1]); h1=O[2*j+1]*th(c8[2*j+1]);
        u16 a=bfb(h0),b=bfb(h1);
        ph[j]=(u32)a|((u32)b<<16);
        pl[j]=(u32)bfb(h0-bff(a))|((u32)bfb(h1-bff(b))<<16);
      }
      char* hp=smc+(32*l+uu)*PB+bg*16;
      *reinterpret_cast<uint4*>(hp)=make_uint4(ph[0],ph[1],ph[2],ph[3]);
      *reinterpret_cast<uint4*>(hp+OFF_BLO)=make_uint4(pl[0],pl[1],pl[2],pl[3]);
    }
    if(tid<32&&it<=TT-3){
      float vv[4]={xreg.x,xreg.y,xreg.z,xreg.w};
      #pragma unroll
      for(int k=0;k<4;k++){
        u16 hb=bfb(vv[k]);
        *reinterpret_cast<u16*>(smc+(64+k)*PB+tid*2)=hb;
        *reinterpret_cast<u16*>(smc+OFF_BLO+(64+k)*PB+tid*2)=bfb(vv[k]-bff(hb));
      }
      int nt=it+3; if(nt>TT-1) nt=TT-1;
      xreg=xg[nt];
    }
    __syncthreads();                      // BAR2: B (h, x) visible
  }

  // head: out[n] = sum_u (h1hi+h1lo)[u][n] * Wout[u] + bout
  if(tid<32){
    float acc=bout[0];
    #pragma unroll 4
    for(int u=0;u<32;u++){
      float h=bff(*reinterpret_cast<u16*>(smc+(32+u)*PB+tid*2))
             +bff(*reinterpret_cast<u16*>(smc+OFF_BLO+(32+u)*PB+tid*2));
      acc=fmaf(h,Wout[u],acc);
    }
    out[blockIdx.x*32+tid]=acc;
  }
}

extern "C" void kernel_launch(void* const* d_in, const int* in_sizes, int n_in,
                              void* d_out, int out_size)
{
  cudaFuncSetAttribute(lstm_k, cudaFuncAttributeMaxDynamicSharedMemorySize, SMEM_SZ);
  lstm_k<<<out_size/32, 256, SMEM_SZ>>>(
    (const float*)d_in[0],(const float*)d_in[1],(const float*)d_in[2],
    (const float*)d_in[3],(const float*)d_in[4],(const float*)d_in[5],
    (const float*)d_in[6],(const float*)d_in[7],(const float*)d_in[8],
    (const float*)d_in[9],(const float*)d_in[10],(float*)d_out);
}

// round 16
// speedup vs baseline: 1.5546x; 1.1908x over previous
#include <cuda_runtime.h>
#include <cuda_bf16.h>
#include <cstdint>
typedef uint32_t u32;
typedef uint16_t u16;

#define TT 512
#define PB 80            // B plane pitch (32 bf16 + pad), conflict-free ldmatrix
#define PG 144           // gates plane pitch (32 f32 + pad)
#define OFF_BLO 6400     // B planes: hi at 0, lo at 6400 (80 rows x 80B)
#define OFF_G0  12800
#define OFF_G1  31232
#define SMEM_SZ 49664

static __device__ __forceinline__ float th(float x){float y;asm("tanh.approx.f32 %0,%1;":"=f"(y):"f"(x));return y;}
static __device__ __forceinline__ float sg(float x){return fmaf(0.5f,th(0.5f*x),0.5f);}
static __device__ __forceinline__ u16 bfb(float v){__nv_bfloat16 h=__float2bfloat16(v);return *reinterpret_cast<u16*>(&h);}
static __device__ __forceinline__ float bff(u16 b){__nv_bfloat16 h=*reinterpret_cast<__nv_bfloat16*>(&b);return __bfloat162float(h);}

#define MMA(d0,d1,d2,d3,a,b0,b1) \
  asm volatile("mma.sync.aligned.m16n8k16.row.col.f32.bf16.bf16.f32 " \
    "{%0,%1,%2,%3},{%4,%5,%6,%7},{%8,%9},{%0,%1,%2,%3};" \
    : "+f"(d0),"+f"(d1),"+f"(d2),"+f"(d3) \
    : "r"((a)[0]),"r"((a)[1]),"r"((a)[2]),"r"((a)[3]),"r"(b0),"r"(b1))

static __device__ __forceinline__ void ldm4(u32* r, u32 a){
  asm volatile("ldmatrix.sync.aligned.m8n8.x4.trans.shared.b16 {%0,%1,%2,%3},[%4];"
    : "=r"(r[0]),"=r"(r[1]),"=r"(r[2]),"=r"(r[3]) : "r"(a));
}
static __device__ __forceinline__ u32 su32(const void*p){u32 a;asm("{.reg .u64 t;cvta.to.shared.u64 t,%1;cvt.u32.u64 %0,t;}":"=r"(a):"l"(p));return a;}

// A0[r][k]: k<32 -> Whh0, k in [64,68) -> Wih0, else 0   (K-chunks 0,1,4)
// A1[r][k]: k<32 -> Wih1, k in [32,64) -> Whh1           (K-chunks 0..3)
static __device__ __forceinline__ float A0v(const float* Whh0,const float* Wih0,int r,int k){
  if(k<32) return Whh0[r*32+k];
  if(k>=64&&k<68) return Wih0[r*4+(k-64)];
  return 0.f;
}
static __device__ __forceinline__ float A1v(const float* Wih1,const float* Whh1,int r,int k){
  return (k<32) ? Wih1[r*32+k] : Whh1[r*32+(k-32)];
}

__global__ __launch_bounds__(512,1)
void lstm_k(const float* __restrict__ x,
            const float* __restrict__ Wih0,const float* __restrict__ Whh0,
            const float* __restrict__ bih0,const float* __restrict__ bhh0,
            const float* __restrict__ Wih1,const float* __restrict__ Whh1,
            const float* __restrict__ bih1,const float* __restrict__ bhh1,
            const float* __restrict__ Wout,const float* __restrict__ bout,
            float* __restrict__ out)
{
  extern __shared__ __align__(16) char smc[];
  const u32 sb = su32(smc);
  const int tid=threadIdx.x, w=tid>>5, lane=tid&31;
  const int mat=w>>3, ws=w&7;                // warpgroup 0 -> D0, 1 -> D1; strip ws
  const int g=lane>>2, tg=lane&3;
  const int r0=16*ws+g, r1=r0+8;
  const bool isg = ((ws>>1)==2);             // rows 64..95 = gate 'g' -> tanh
  const int nkc = mat ? 4 : 3;               // K-chunks this warpgroup needs

  // zero both B planes (h=0 init, x pad rows stay 0)
  for(int i=tid;i<800;i+=512) reinterpret_cast<uint4*>(smc)[i]=make_uint4(0,0,0,0);

  // ---- A fragments in registers (hi/lo bf16 split): one matrix per warpgroup ----
  u32 ah[4][4], al[4][4];
  {
    const int kb0[3]={0,16,64};
    #pragma unroll
    for(int m=0;m<4;m++)
      #pragma unroll
      for(int j=0;j<4;j++){
        int rr=(j&1)?r1:r0;
        float v0,v1;
        if(mat==0){
          if(m<3){ int kk=kb0[m]+2*tg+((j>>1)*8);
                   v0=A0v(Whh0,Wih0,rr,kk); v1=A0v(Whh0,Wih0,rr,kk+1);}
          else   { v0=0.f; v1=0.f; }
        } else {
          int kk=16*m+2*tg+((j>>1)*8);
          v0=A1v(Wih1,Whh1,rr,kk); v1=A1v(Wih1,Whh1,rr,kk+1);
        }
        u16 h0=bfb(v0),h1=bfb(v1);
        ah[m][j]=(u32)h0|((u32)h1<<16);
        al[m][j]=(u32)bfb(v0-bff(h0))|((u32)bfb(v1-bff(h1))<<16);
      }
  }
  const float bA = mat ? bih1[r0]+bhh1[r0] : bih0[r0]+bhh0[r0];
  const float bB = mat ? bih1[r1]+bhh1[r1] : bih0[r1]+bhh0[r1];

  // update-task mapping: thread -> (layer l, unit uu, batches 4*bg..4*bg+3)
  const int l=tid>>8, uu=(tid>>3)&31, bg=tid&7;
  float c4[4];
  #pragma unroll
  for(int i=0;i<4;++i) c4[i]=0.f;

  // ldmatrix per-lane base offset
  const int lj=lane>>3, lr=lane&7;
  const u32 lmoff=(u32)((((lj&1)*8+lr)*PB) + ((lj>>1)*16));
  // physical K-chunk row offsets for this warpgroup's local chunk index
  const u32 kcrow[4]={0u,(u32)(16*PB),(u32)(mat?32*PB:64*PB),(u32)(48*PB)};

  __syncthreads();

  // x stream: thread n<32 owns batch n
  const float4* xg = reinterpret_cast<const float4*>(x) + ((size_t)(blockIdx.x*32+tid))*TT;
  float4 xreg=make_float4(0,0,0,0);
  if(tid<32){
    float4 v=xg[0]; float vv[4]={v.x,v.y,v.z,v.w};
    #pragma unroll
    for(int k=0;k<4;k++){
      u16 hb=bfb(vv[k]);
      *reinterpret_cast<u16*>(smc+(64+k)*PB+tid*2)=hb;
      *reinterpret_cast<u16*>(smc+OFF_BLO+(64+k)*PB+tid*2)=bfb(vv[k]-bff(hb));
    }
    xreg=xg[1];
  }
  __syncthreads();

  char* const gbase = smc + (mat?OFF_G1:OFF_G0) + r0*PG + 2*tg*4;

  for(int it=-1;it<TT;++it){
    const bool do0=(it<TT-1), do1=(it>=0);
    const bool act = mat ? do1 : do0;

    if(act){
      #pragma unroll
      for(int ncp=0;ncp<4;ncp+=2){
        u32 bh[4][4], bl[4][4];
        #pragma unroll
        for(int kc=0;kc<4;kc++){
          if(kc<nkc){
            u32 base=lmoff+kcrow[kc]+(u32)(ncp*16);
            ldm4(bh[kc], sb+base);
            ldm4(bl[kc], sb+OFF_BLO+base);
          }
        }
        #pragma unroll
        for(int ns=0;ns<2;++ns){
          const int nc=ncp+ns;
          float d0=bA,d1=bA,d2=bB,d3=bB;
          #pragma unroll
          for(int m=0;m<4;m++){
            if(m<nkc){
              MMA(d0,d1,d2,d3,ah[m],bh[m][2*ns],bh[m][2*ns+1]);
              MMA(d0,d1,d2,d3,ah[m],bl[m][2*ns],bl[m][2*ns+1]);
              MMA(d0,d1,d2,d3,al[m],bh[m][2*ns],bh[m][2*ns+1]);
            }
          }
          float e0,e1,e2,e3;
          if(isg){e0=th(d0);e1=th(d1);e2=th(d2);e3=th(d3);}
          else   {e0=sg(d0);e1=sg(d1);e2=sg(d2);e3=sg(d3);}
          char* gp=gbase+nc*32;
          *reinterpret_cast<float2*>(gp)=make_float2(e0,e1);
          *reinterpret_cast<float2*>(gp+8*PG)=make_float2(e2,e3);
        }
      }
    }
    __syncthreads();                      // BAR1: gates visible

    if((l==0&&do0)||(l==1&&do1)){
      const char* gp=smc+(l?OFF_G1:OFF_G0)+uu*PG+bg*16;
      float4 I4=*reinterpret_cast<const float4*>(gp);
      float4 F4=*reinterpret_cast<const float4*>(gp+32*PG);
      float4 G4=*reinterpret_cast<const float4*>(gp+64*PG);
      float4 O4=*reinterpret_cast<const float4*>(gp+96*PG);
      float I[4]={I4.x,I4.y,I4.z,I4.w};
      float F[4]={F4.x,F4.y,F4.z,F4.w};
      float Gv[4]={G4.x,G4.y,G4.z,G4.w};
      float O[4]={O4.x,O4.y,O4.z,O4.w};
      u32 ph[2],pl[2];
      #pragma unroll
      for(int j=0;j<2;j++){
        float h0,h1;
        c4[2*j]  =fmaf(F[2*j],  c4[2*j],  I[2*j]*Gv[2*j]);     h0=O[2*j]*th(c4[2*j]);
        c4[2*j+1]=fmaf(F[2*j+1],c4[2*j+1],I[2*j+1]*Gv[2*j+1]); h1=O[2*j+1]*th(c4[2*j+1]);
        u16 a=bfb(h0),b=bfb(h1);
        ph[j]=(u32)a|((u32)b<<16);
        pl[j]=(u32)bfb(h0-bff(a))|((u32)bfb(h1-bff(b))<<16);
      }
      char* hp=smc+(32*l+uu)*PB+bg*8;
      *reinterpret_cast<uint2*>(hp)=make_uint2(ph[0],ph[1]);
      *reinterpret_cast<uint2*>(hp+OFF_BLO)=make_uint2(pl[0],pl[1]);
    }
    if(tid<32&&it<=TT-3){
      float vv[4]={xreg.x,xreg.y,xreg.z,xreg.w};
      #pragma unroll
      for(int k=0;k<4;k++){
        u16 hb=bfb(vv[k]);
        *reinterpret_cast<u16*>(smc+(64+k)*PB+tid*2)=hb;
        *reinterpret_cast<u16*>(smc+OFF_BLO+(64+k)*PB+tid*2)=bfb(vv[k]-bff(hb));
      }
      int nt=it+3; if(nt>TT-1) nt=TT-1;
      xreg=xg[nt];
    }
    __syncthreads();                      // BAR2: B (h, x) visible
  }

  // head: out[n] = sum_u (h1hi+h1lo)[u][n] * Wout[u] + bout
  if(tid<32){
    float acc=bout[0];
    #pragma unroll 4
    for(int u=0;u<32;u++){
      float h=bff(*reinterpret_cast<u16*>(smc+(32+u)*PB+tid*2))
             +bff(*reinterpret_cast<u16*>(smc+OFF_BLO+(32+u)*PB+tid*2));
      acc=fmaf(h,Wout[u],acc);
    }
    out[blockIdx.x*32+tid]=acc;
  }
}

extern "C" void kernel_launch(void* const* d_in, const int* in_sizes, int n_in,
                              void* d_out, int out_size)
{
  cudaFuncSetAttribute(lstm_k, cudaFuncAttributeMaxDynamicSharedMemorySize, SMEM_SZ);
  lstm_k<<<out_size/32, 512, SMEM_SZ>>>(
    (const float*)d_in[0],(const float*)d_in[1],(const float*)d_in[2],
    (const float*)d_in[3],(const float*)d_in[4],(const float*)d_in[5],
    (const float*)d_in[6],(const float*)d_in[7],(const float*)d_in[8],
    (const float*)d_in[9],(const float*)d_in[10],(float*)d_out);
}

// round 17
// speedup vs baseline: 2.0875x; 1.3429x over previous
#include <cuda_runtime.h>
#include <cuda_bf16.h>
#include <cstdint>
typedef uint32_t u32;
typedef uint16_t u16;

#define TT 512
#define NB 16            // batches per block
#define PB 80            // B plane pitch (bytes)
#define PG 80            // gates plane pitch (16 f32 + pad)
#define OFF_BLO 6400     // B planes: hi at 0, lo at 6400
#define OFF_G0  12800
#define OFF_G1  23040
#define SMEM_SZ 33280

static __device__ __forceinline__ float th(float x){float y;asm("tanh.approx.f32 %0,%1;":"=f"(y):"f"(x));return y;}
static __device__ __forceinline__ float sg(float x){return fmaf(0.5f,th(0.5f*x),0.5f);}
static __device__ __forceinline__ u16 bfb(float v){__nv_bfloat16 h=__float2bfloat16(v);return *reinterpret_cast<u16*>(&h);}
static __device__ __forceinline__ float bff(u16 b){__nv_bfloat16 h=*reinterpret_cast<__nv_bfloat16*>(&b);return __bfloat162float(h);}

#define MMA(d,a,b0,b1) \
  asm volatile("mma.sync.aligned.m16n8k16.row.col.f32.bf16.bf16.f32 " \
    "{%0,%1,%2,%3},{%4,%5,%6,%7},{%8,%9},{%0,%1,%2,%3};" \
    : "+f"((d)[0]),"+f"((d)[1]),"+f"((d)[2]),"+f"((d)[3]) \
    : "r"((a)[0]),"r"((a)[1]),"r"((a)[2]),"r"((a)[3]),"r"(b0),"r"(b1))

static __device__ __forceinline__ void ldm4(u32* r, u32 a){
  asm volatile("ldmatrix.sync.aligned.m8n8.x4.trans.shared.b16 {%0,%1,%2,%3},[%4];"
    : "=r"(r[0]),"=r"(r[1]),"=r"(r[2]),"=r"(r[3]) : "r"(a));
}
static __device__ __forceinline__ u32 su32(const void*p){u32 a;asm("{.reg .u64 t;cvta.to.shared.u64 t,%1;cvt.u32.u64 %0,t;}":"=r"(a):"l"(p));return a;}

// A0[r][k]: k<32 -> Whh0, k in [64,68) -> Wih0, else 0   (K-chunks 0,1,4)
// A1[r][k]: k<32 -> Wih1, k in [32,64) -> Whh1           (K-chunks 0..3)
static __device__ __forceinline__ float A0v(const float* Whh0,const float* Wih0,int r,int k){
  if(k<32) return Whh0[r*32+k];
  if(k>=64&&k<68) return Wih0[r*4+(k-64)];
  return 0.f;
}
static __device__ __forceinline__ float A1v(const float* Wih1,const float* Whh1,int r,int k){
  return (k<32) ? Wih1[r*32+k] : Whh1[r*32+(k-32)];
}

__global__ __launch_bounds__(256,2)
void lstm_k(const float* __restrict__ x,
            const float* __restrict__ Wih0,const float* __restrict__ Whh0,
            const float* __restrict__ bih0,const float* __restrict__ bhh0,
            const float* __restrict__ Wih1,const float* __restrict__ Whh1,
            const float* __restrict__ bih1,const float* __restrict__ bhh1,
            const float* __restrict__ Wout,const float* __restrict__ bout,
            float* __restrict__ out)
{
  extern __shared__ __align__(16) char smc[];
  const u32 sb = su32(smc);
  const int tid=threadIdx.x, w=tid>>5, lane=tid&31;
  const int mat=w>>2, p=w&3;                 // warp: matrix (D0/D1), gate-group p
  const int g=lane>>2, tg=lane&3;
  const bool isg = (p==2);                   // gate-group 2 -> tanh
  const int nkc = mat ? 4 : 3;

  // zero B planes (h=0 init, x pad rows 68-79 stay 0)
  for(int i=tid;i<800;i+=256) reinterpret_cast<uint4*>(smc)[i]=make_uint4(0,0,0,0);

  // ---- A fragments in registers (hi/lo bf16 split): 2 row-strips per warp ----
  u32 ah[2][4][4], al[2][4][4];
  {
    const int kb0[3]={0,16,64};
    #pragma unroll
    for(int s=0;s<2;s++){
      const int rbase=32*p+16*s;
      #pragma unroll
      for(int m=0;m<4;m++)
        #pragma unroll
        for(int j=0;j<4;j++){
          int rr=rbase+g+((j&1)?8:0);
          float v0,v1;
          if(mat==0){
            if(m<3){ int kk=kb0[m]+2*tg+((j>>1)*8);
                     v0=A0v(Whh0,Wih0,rr,kk); v1=A0v(Whh0,Wih0,rr,kk+1);}
            else   { v0=0.f; v1=0.f; }
          } else {
            int kk=16*m+2*tg+((j>>1)*8);
            v0=A1v(Wih1,Whh1,rr,kk); v1=A1v(Wih1,Whh1,rr,kk+1);
          }
          u16 h0=bfb(v0),h1=bfb(v1);
          ah[s][m][j]=(u32)h0|((u32)h1<<16);
          al[s][m][j]=(u32)bfb(v0-bff(h0))|((u32)bfb(v1-bff(h1))<<16);
        }
    }
  }
  float bias[2][2];
  #pragma unroll
  for(int s=0;s<2;s++){
    const int rbase=32*p+16*s;
    bias[s][0]= mat ? bih1[rbase+g]+bhh1[rbase+g]     : bih0[rbase+g]+bhh0[rbase+g];
    bias[s][1]= mat ? bih1[rbase+8+g]+bhh1[rbase+8+g] : bih0[rbase+8+g]+bhh0[rbase+8+g];
  }

  // update-task mapping: thread -> (layer l, unit uu, batches 4*bg..4*bg+3)
  const int l=tid>>7, uu=(tid>>2)&31, bg=tid&3;
  float c4[4];
  #pragma unroll
  for(int i=0;i<4;++i) c4[i]=0.f;

  // ldmatrix per-lane base offset (x4 trans: 16 rows x 16 cols = all NB batches)
  const int lj=lane>>3, lr=lane&7;
  const u32 lmoff=(u32)((((lj&1)*8+lr)*PB) + ((lj>>1)*16));
  const u32 kcrow[4]={0u,(u32)(16*PB),(u32)(mat?32*PB:64*PB),(u32)(48*PB)};

  __syncthreads();

  // x stream: thread n<NB owns batch n
  const float4* xg = reinterpret_cast<const float4*>(x) + ((size_t)(blockIdx.x*NB+tid))*TT;
  float4 xreg=make_float4(0,0,0,0);
  if(tid<NB){
    float4 v=xg[0]; float vv[4]={v.x,v.y,v.z,v.w};
    #pragma unroll
    for(int k=0;k<4;k++){
      u16 hb=bfb(vv[k]);
      *reinterpret_cast<u16*>(smc+(64+k)*PB+tid*2)=hb;
      *reinterpret_cast<u16*>(smc+OFF_BLO+(64+k)*PB+tid*2)=bfb(vv[k]-bff(hb));
    }
    xreg=xg[1];
  }
  __syncthreads();

  char* const gplane = smc + (mat?OFF_G1:OFF_G0);

  for(int it=-1;it<TT;++it){
    const bool do0=(it<TT-1), do1=(it>=0);
    const bool act = mat ? do1 : do0;

    if(act){
      float d[2][2][4];           // [strip][n-half][4]
      #pragma unroll
      for(int s=0;s<2;s++)
        #pragma unroll
        for(int ns=0;ns<2;ns++){
          d[s][ns][0]=bias[s][0]; d[s][ns][1]=bias[s][0];
          d[s][ns][2]=bias[s][1]; d[s][ns][3]=bias[s][1];
        }
      #pragma unroll
      for(int m=0;m<4;m++){
        if(m<nkc){
          u32 bh[4], bl[4];
          u32 base=lmoff+kcrow[m];
          ldm4(bh, sb+base);
          ldm4(bl, sb+OFF_BLO+base);
          #pragma unroll
          for(int s=0;s<2;s++)
            #pragma unroll
            for(int ns=0;ns<2;ns++){
              MMA(d[s][ns],ah[s][m],bh[2*ns],bh[2*ns+1]);
              MMA(d[s][ns],ah[s][m],bl[2*ns],bl[2*ns+1]);
              MMA(d[s][ns],al[s][m],bh[2*ns],bh[2*ns+1]);
            }
        }
      }
      // epilogue: activation + store gates
      #pragma unroll
      for(int s=0;s<2;s++){
        const int rbase=32*p+16*s;
        char* gb = gplane + (rbase+g)*PG + 2*tg*4;
        #pragma unroll
        for(int ns=0;ns<2;ns++){
          float e0,e1,e2,e3;
          if(isg){e0=th(d[s][ns][0]);e1=th(d[s][ns][1]);e2=th(d[s][ns][2]);e3=th(d[s][ns][3]);}
          else   {e0=sg(d[s][ns][0]);e1=sg(d[s][ns][1]);e2=sg(d[s][ns][2]);e3=sg(d[s][ns][3]);}
          *reinterpret_cast<float2*>(gb+ns*32)=make_float2(e0,e1);
          *reinterpret_cast<float2*>(gb+ns*32+8*PG)=make_float2(e2,e3);
        }
      }
    }
    __syncthreads();                      // BAR1: gates visible

    if((l==0&&do0)||(l==1&&do1)){
      const char* gp=smc+(l?OFF_G1:OFF_G0)+uu*PG+bg*16;
      float4 I4=*reinterpret_cast<const float4*>(gp);
      float4 F4=*reinterpret_cast<const float4*>(gp+32*PG);
      float4 G4=*reinterpret_cast<const float4*>(gp+64*PG);
      float4 O4=*reinterpret_cast<const float4*>(gp+96*PG);
      float I[4]={I4.x,I4.y,I4.z,I4.w};
      float F[4]={F4.x,F4.y,F4.z,F4.w};
      float Gv[4]={G4.x,G4.y,G4.z,G4.w};
      float O[4]={O4.x,O4.y,O4.z,O4.w};
      u32 ph[2],pl[2];
      #pragma unroll
      for(int j=0;j<2;j++){
        float h0,h1;
        c4[2*j]  =fmaf(F[2*j],  c4[2*j],  I[2*j]*Gv[2*j]);     h0=O[2*j]*th(c4[2*j]);
        c4[2*j+1]=fmaf(F[2*j+1],c4[2*j+1],I[2*j+1]*Gv[2*j+1]); h1=O[2*j+1]*th(c4[2*j+1]);
        u16 a=bfb(h0),b=bfb(h1);
        ph[j]=(u32)a|((u32)b<<16);
        pl[j]=(u32)bfb(h0-bff(a))|((u32)bfb(h1-bff(b))<<16);
      }
      char* hp=smc+(32*l+uu)*PB+bg*8;
      *reinterpret_cast<uint2*>(hp)=make_uint2(ph[0],ph[1]);
      *reinterpret_cast<uint2*>(hp+OFF_BLO)=make_uint2(pl[0],pl[1]);
    }
    if(tid<NB&&it<=TT-3){
      float vv[4]={xreg.x,xreg.y,xreg.z,xreg.w};
      #pragma unroll
      for(int k=0;k<4;k++){
        u16 hb=bfb(vv[k]);
        *reinterpret_cast<u16*>(smc+(64+k)*PB+tid*2)=hb;
        *reinterpret_cast<u16*>(smc+OFF_BLO+(64+k)*PB+tid*2)=bfb(vv[k]-bff(hb));
      }
      int nt=it+3; if(nt>TT-1) nt=TT-1;
      xreg=xg[nt];
    }
    __syncthreads();                      // BAR2: B (h, x) visible
  }

  // head: out[n] = sum_u (h1hi+h1lo)[u][n] * Wout[u] + bout
  if(tid<NB){
    float acc=bout[0];
    #pragma unroll 4
    for(int u=0;u<32;u++){
      float h=bff(*reinterpret_cast<u16*>(smc+(32+u)*PB+tid*2))
             +bff(*reinterpret_cast<u16*>(smc+OFF_BLO+(32+u)*PB+tid*2));
      acc=fmaf(h,Wout[u],acc);
    }
    out[blockIdx.x*NB+tid]=acc;
  }
}

extern "C" void kernel_launch(void* const* d_in, const int* in_sizes, int n_in,
                              void* d_out, int out_size)
{
  cudaFuncSetAttribute(lstm_k, cudaFuncAttributeMaxDynamicSharedMemorySize, SMEM_SZ);
  lstm_k<<<out_size/NB, 256, SMEM_SZ>>>(
    (const float*)d_in[0],(const float*)d_in[1],(const float*)d_in[2],
    (const float*)d_in[3],(const float*)d_in[4],(const float*)d_in[5],
    (const float*)d_in[6],(const float*)d_in[7],(const float*)d_in[8],
    (const float*)d_in[9],(const float*)d_in[10],(float*)d_out);
}